// round 4
// baseline (speedup 1.0000x reference)
#include <cuda_runtime.h>
#include <math.h>

#define B_ 4
#define C_ 64
#define H_ 128
#define W_ 128
#define HW_ (H_*W_)
#define O_ 64

// Packed f32x2 helpers (Blackwell)
#define FMA2(acc, a, b) asm("fma.rn.f32x2 %0, %1, %2, %0;" : "+l"(acc) : "l"(a), "l"(b))
#define DUP2(dst, f)    asm("mov.b64 %0, {%1, %1};" : "=l"(dst) : "f"(f))
#define UNPK2(lo, hi, v) asm("mov.b64 {%0, %1}, %2;" : "=f"(lo), "=f"(hi) : "l"(v))

// Scratch
__device__ __align__(16) float g_xt[B_*HW_*C_];       // x in NHWC
__device__ __align__(16) float g_off[B_*HW_*18];      // offsets [b][h][w][18]
__device__ __align__(16) float g_wdt2[9*64*128];      // w_def [k][c][o dup-pairs]
__device__ __align__(16) float g_partial[256*2*16*2]; // [blk][half][group][2]
__device__ __align__(16) float g_stats[B_*16*2];      // mu, inv_std

// ---------------- K0: NCHW -> NHWC transpose ----------------
__global__ void k_transpose(const float* __restrict__ x) {
    __shared__ float tile[32][33];
    int b  = blockIdx.z;
    int c0 = blockIdx.y * 32;
    int p0 = blockIdx.x * 32;
    int tx = threadIdx.x, ty = threadIdx.y;
    tile[ty][tx] = x[(b*C_ + c0 + ty)*HW_ + p0 + tx];
    __syncthreads();
    g_xt[(b*HW_ + p0 + ty)*C_ + c0 + tx] = tile[tx][ty];
}

// ---------------- Kw: w_def [o][c][3][3] -> [k][c][o dup] ----------------
__global__ void k_wreorder(const float* __restrict__ w_def) {
    int i = blockIdx.x * 256 + threadIdx.x;
    if (i < 9*64*64) {
        int o = i & 63;
        int c = (i >> 6) & 63;
        int k = i >> 12;
        float w = w_def[(o*64 + c)*9 + k];
        g_wdt2[(k*64 + c)*128 + o*2 + 0] = w;
        g_wdt2[(k*64 + c)*128 + o*2 + 1] = w;
    }
}

// ---------------- K1: offset conv (64 -> 18 ch, 3x3, pad 1) ----------------
__global__ void __launch_bounds__(128) k_offconv(const float* __restrict__ x,
                                                 const float* __restrict__ w_off,
                                                 const float* __restrict__ b_off) {
    __shared__ __align__(16) float ws[64*9*20];
    int h = blockIdx.x, b = blockIdx.y;
    int tid = threadIdx.x;

    for (int i = tid; i < 64*9*20; i += 128) ws[i] = 0.f;
    __syncthreads();
    for (int i = tid; i < 64*9*18; i += 128) {
        int o = i % 18;
        int cj = i / 18;
        int c = cj / 9, j = cj % 9;
        ws[cj*20 + o] = w_off[(o*64 + c)*9 + j];
    }
    __syncthreads();

    int w = tid;
    unsigned long long acc[10];
#pragma unroll
    for (int q = 0; q < 10; q++) acc[q] = 0ull;

    const float* xb = x + (size_t)b * C_ * HW_;
    bool wl = (w > 0), wr = (w < W_-1);

    for (int c = 0; c < C_; c++) {
        const float* xc = xb + c*HW_;
        float xv[9];
#pragma unroll
        for (int jy = 0; jy < 3; jy++) {
            int y = h + jy - 1;
            bool yv = (y >= 0 && y < H_);
            const float* row = xc + y*W_;
            xv[jy*3+0] = (yv && wl) ? row[w-1] : 0.f;
            xv[jy*3+1] =  yv        ? row[w]   : 0.f;
            xv[jy*3+2] = (yv && wr) ? row[w+1] : 0.f;
        }
#pragma unroll
        for (int j = 0; j < 9; j++) {
            unsigned long long v2;
            DUP2(v2, xv[j]);
            const ulonglong2* wp = (const ulonglong2*)&ws[(c*9 + j)*20];
#pragma unroll
            for (int q = 0; q < 5; q++) {
                ulonglong2 wv = wp[q];
                FMA2(acc[2*q+0], wv.x, v2);
                FMA2(acc[2*q+1], wv.y, v2);
            }
        }
    }

    float* op = &g_off[((size_t)(b*H_ + h)*W_ + w)*18];
#pragma unroll
    for (int q = 0; q < 9; q++) {
        float lo, hi;
        UNPK2(lo, hi, acc[q]);
        op[2*q+0] = lo + b_off[2*q+0];
        op[2*q+1] = hi + b_off[2*q+1];
    }
}

// ---------------- K2: pipelined deformable sample + GEMM ----------------
// Block = 2 rows (256 px), 256 threads, 2 blocks/SM.
// 18 units (tap x c-half). Phase p: gather(unit p) interleaved with GEMM(unit p-1).
// smem (floats): sbuf0[32][256], sbuf1[32][256], addr x2, bilinear-w x2.
#define SBUF0  0
#define SBUF1  8192
#define SADDR0 16384
#define SADDR1 17408
#define SBW0   18432
#define SBW1   19456
#define SMF    20480   // 80 KB

__device__ __forceinline__ void comp_addr(float* sm, int k, int par,
                                          int h_a, int w_a, const float* offp, int tid) {
    int*   sa  = (int*)(sm + (par ? SADDR1 : SADDR0));
    float* swt = sm + (par ? SBW1 : SBW0);
    float dy = offp[2*k], dx = offp[2*k+1];
    float py  = (float)(h_a + k/3 - 1) + dy;
    float pxf = (float)(w_a + k%3 - 1) + dx;
    float y0f = floorf(py), x0f = floorf(pxf);
    float wy = py - y0f, wx = pxf - x0f;
    int y0 = (int)y0f, x0 = (int)x0f;
    int y1 = y0 + 1, x1 = x0 + 1;
    float vy0 = (y0 >= 0 && y0 < H_) ? 1.f : 0.f;
    float vy1 = (y1 >= 0 && y1 < H_) ? 1.f : 0.f;
    float vx0 = (x0 >= 0 && x0 < W_) ? 1.f : 0.f;
    float vx1 = (x1 >= 0 && x1 < W_) ? 1.f : 0.f;
    int y0c = min(max(y0,0),H_-1), y1c = min(max(y1,0),H_-1);
    int x0c = min(max(x0,0),W_-1), x1c = min(max(x1,0),W_-1);
    sa[0*256+tid] = (y0c*W_ + x0c)*C_;  swt[0*256+tid] = (1.f-wy)*(1.f-wx)*vy0*vx0;
    sa[1*256+tid] = (y0c*W_ + x1c)*C_;  swt[1*256+tid] = (1.f-wy)*wx*vy0*vx1;
    sa[2*256+tid] = (y1c*W_ + x0c)*C_;  swt[2*256+tid] = wy*(1.f-wx)*vy1*vx0;
    sa[3*256+tid] = (y1c*W_ + x1c)*C_;  swt[3*256+tid] = wy*wx*vy1*vx1;
}

__global__ void __launch_bounds__(256, 2) k_main(const float* __restrict__ b_def,
                                                 float* __restrict__ out) {
    extern __shared__ float sm[];
    int hb = blockIdx.x;
    int b  = blockIdx.y;
    int tid = threadIdx.x;
    int warp = tid >> 5, col = tid & 31;
    int halfw = warp >> 2;
    int o0 = (warp & 3) * 16;
    int i4 = halfw*32 + col;
    int g8 = tid >> 3, l8 = tid & 7;

    int row_a = tid >> 7;
    int w_a = tid & 127;
    int h_a = hb*2 + row_a;
    const float* offp = g_off + ((size_t)((b*H_ + h_a)*W_) + w_a)*18;
    const float* xb = g_xt + (size_t)b * HW_ * C_;

    unsigned long long acc[16][2];
#pragma unroll
    for (int i = 0; i < 16; i++) { acc[i][0] = 0ull; acc[i][1] = 0ull; }

    comp_addr(sm, 0, 0, h_a, w_a, offp, tid);
    __syncthreads();

#pragma unroll 1
    for (int p = 0; p < 19; p++) {
        bool do_g = (p < 18), do_m = (p >= 1);
        int kg = p >> 1, hg = p & 1;
        const int*   sa  = (const int*)(sm + ((kg&1) ? SADDR1 : SADDR0));
        const float* swt = sm + ((kg&1) ? SBW1 : SBW0);
        float*       sbw = sm + ((p&1)  ? SBUF1 : SBUF0);
        const float* sbr = sm + (((p-1)&1) ? SBUF1 : SBUF0);
        int um = do_m ? (p-1) : 0;
        int km = um >> 1, hm = um & 1;
        const float* wbase = g_wdt2 + (size_t)(km*64 + hm*32)*128 + o0*2;
        int chb = hg*32 + l8*4;

#pragma unroll
        for (int pass = 0; pass < 8; pass++) {
            int pxi = pass*32 + g8;
            float4 v0, v1, v2, v3;
            float bw0, bw1, bw2, bw3;
            if (do_g) {
                int a0 = sa[pxi], a1 = sa[256+pxi], a2 = sa[512+pxi], a3 = sa[768+pxi];
                bw0 = swt[pxi]; bw1 = swt[256+pxi]; bw2 = swt[512+pxi]; bw3 = swt[768+pxi];
                v0 = *(const float4*)(xb + a0 + chb);
                v1 = *(const float4*)(xb + a1 + chb);
                v2 = *(const float4*)(xb + a2 + chb);
                v3 = *(const float4*)(xb + a3 + chb);
            }
            if (do_m) {
#pragma unroll
                for (int j = 0; j < 4; j++) {
                    int cc = pass*4 + j;
                    ulonglong2 s2 = *(const ulonglong2*)&sbr[cc*256 + ((i4 ^ pass) << 2)];
                    const ulonglong2* wp = (const ulonglong2*)(wbase + cc*128);
                    ulonglong2 wA = wp[0], wB = wp[1], wC = wp[2], wD = wp[3];
                    FMA2(acc[0][0],  wA.x, s2.x); FMA2(acc[0][1],  wA.x, s2.y);
                    FMA2(acc[1][0],  wA.y, s2.x); FMA2(acc[1][1],  wA.y, s2.y);
                    FMA2(acc[2][0],  wB.x, s2.x); FMA2(acc[2][1],  wB.x, s2.y);
                    FMA2(acc[3][0],  wB.y, s2.x); FMA2(acc[3][1],  wB.y, s2.y);
                    FMA2(acc[4][0],  wC.x, s2.x); FMA2(acc[4][1],  wC.x, s2.y);
                    FMA2(acc[5][0],  wC.y, s2.x); FMA2(acc[5][1],  wC.y, s2.y);
                    FMA2(acc[6][0],  wD.x, s2.x); FMA2(acc[6][1],  wD.x, s2.y);
                    FMA2(acc[7][0],  wD.y, s2.x); FMA2(acc[7][1],  wD.y, s2.y);
                    const ulonglong2* wq = (const ulonglong2*)(wbase + cc*128 + 16);
                    ulonglong2 wE = wq[0], wF = wq[1], wG = wq[2], wH = wq[3];
                    FMA2(acc[8][0],  wE.x, s2.x); FMA2(acc[8][1],  wE.x, s2.y);
                    FMA2(acc[9][0],  wE.y, s2.x); FMA2(acc[9][1],  wE.y, s2.y);
                    FMA2(acc[10][0], wF.x, s2.x); FMA2(acc[10][1], wF.x, s2.y);
                    FMA2(acc[11][0], wF.y, s2.x); FMA2(acc[11][1], wF.y, s2.y);
                    FMA2(acc[12][0], wG.x, s2.x); FMA2(acc[12][1], wG.x, s2.y);
                    FMA2(acc[13][0], wG.y, s2.x); FMA2(acc[13][1], wG.y, s2.y);
                    FMA2(acc[14][0], wH.x, s2.x); FMA2(acc[14][1], wH.x, s2.y);
                    FMA2(acc[15][0], wH.y, s2.x); FMA2(acc[15][1], wH.y, s2.y);
                }
            }
            if (do_g) {
                float sx = bw0*v0.x + bw1*v1.x + bw2*v2.x + bw3*v3.x;
                float sy = bw0*v0.y + bw1*v1.y + bw2*v2.y + bw3*v3.y;
                float sz = bw0*v0.z + bw1*v1.z + bw2*v2.z + bw3*v3.z;
                float sw = bw0*v0.w + bw1*v1.w + bw2*v2.w + bw3*v3.w;
                int scg = (((pxi>>2) ^ l8) << 2) + (pxi & 3);
                float* d = &sbw[(l8*4)*256 + scg];
                d[0]   = sx;
                d[256] = sy;
                d[512] = sz;
                d[768] = sw;
            }
        }
        if ((p & 1) && p < 17) comp_addr(sm, (p+1)>>1, ((p+1)>>1)&1, h_a, w_a, offp, tid);
        __syncthreads();
    }

    // ---- epilogue: bias, store pre-GN, per-group partials ----
    float sg[4] = {0,0,0,0}, qg[4] = {0,0,0,0};
    int h_out = hb*2 + halfw;
    float* outb = out + (size_t)b * O_ * HW_ + h_out*W_ + col*4;
#pragma unroll
    for (int i = 0; i < 16; i++) {
        int o = o0 + i;
        float bo = b_def[o];
        float4 v;
        UNPK2(v.x, v.y, acc[i][0]);
        UNPK2(v.z, v.w, acc[i][1]);
        v.x += bo; v.y += bo; v.z += bo; v.w += bo;
        *(float4*)(outb + (size_t)o * HW_) = v;
        int gi = i >> 2;
        sg[gi] += v.x + v.y + v.z + v.w;
        qg[gi] += v.x*v.x + v.y*v.y + v.z*v.z + v.w*v.w;
    }
#pragma unroll
    for (int off = 16; off > 0; off >>= 1) {
#pragma unroll
        for (int gi = 0; gi < 4; gi++) {
            sg[gi] += __shfl_xor_sync(0xffffffffu, sg[gi], off);
            qg[gi] += __shfl_xor_sync(0xffffffffu, qg[gi], off);
        }
    }
    if (col == 0) {
        int blk = b*64 + hb;
        float* pp = &g_partial[(size_t)((blk*2 + halfw)*16)*2];
#pragma unroll
        for (int gi = 0; gi < 4; gi++) {
            int grp = (o0 >> 2) + gi;
            pp[grp*2 + 0] = sg[gi];
            pp[grp*2 + 1] = qg[gi];
        }
    }
}

// ---------------- K3: finalize GN stats ----------------
__global__ void k_stats() {
    int t = threadIdx.x;
    if (t >= 64) return;
    int b = t >> 4, gg = t & 15;
    float s = 0.f, q = 0.f;
    for (int e = 0; e < 128; e++) {
        int blk = b*64 + (e >> 1);
        const float* pp = &g_partial[(size_t)((blk*2 + (e&1))*16 + gg)*2];
        s += pp[0];
        q += pp[1];
    }
    const float N = 4.f * (float)HW_;
    float mu = s / N;
    float var = q / N - mu*mu;
    g_stats[t*2 + 0] = mu;
    g_stats[t*2 + 1] = rsqrtf(var + 1e-5f);
}

// ---------------- K4: GN affine + LeakyReLU ----------------
__global__ void k_norm(float* __restrict__ out,
                       const float* __restrict__ gn_w,
                       const float* __restrict__ gn_b) {
    int i = blockIdx.x * 256 + threadIdx.x;
    int base = i * 4;
    int c = (base >> 14) & 63;
    int b = base >> 20;
    int g = c >> 2;
    float mu  = g_stats[(b*16 + g)*2 + 0];
    float inv = g_stats[(b*16 + g)*2 + 1];
    float sc = gn_w[c] * inv;
    float sh = gn_b[c] - mu * sc;
    float4 v = ((float4*)out)[i];
    v.x = v.x*sc + sh; v.x = (v.x >= 0.f) ? v.x : 0.2f*v.x;
    v.y = v.y*sc + sh; v.y = (v.y >= 0.f) ? v.y : 0.2f*v.y;
    v.z = v.z*sc + sh; v.z = (v.z >= 0.f) ? v.z : 0.2f*v.z;
    v.w = v.w*sc + sh; v.w = (v.w >= 0.f) ? v.w : 0.2f*v.w;
    ((float4*)out)[i] = v;
}

extern "C" void kernel_launch(void* const* d_in, const int* in_sizes, int n_in,
                              void* d_out, int out_size) {
    const float* x     = (const float*)d_in[0];
    const float* w_off = (const float*)d_in[1];
    const float* b_off = (const float*)d_in[2];
    const float* w_def = (const float*)d_in[3];
    const float* b_def = (const float*)d_in[4];
    const float* gn_w  = (const float*)d_in[5];
    const float* gn_b  = (const float*)d_in[6];
    float* out = (float*)d_out;

    cudaFuncSetAttribute(k_main, cudaFuncAttributeMaxDynamicSharedMemorySize,
                         SMF * (int)sizeof(float));

    k_transpose<<<dim3(HW_/32, C_/32, B_), dim3(32, 32)>>>(x);
    k_wreorder<<<144, 256>>>(w_def);
    k_offconv<<<dim3(H_, B_), 128>>>(x, w_off, b_off);
    k_main<<<dim3(H_/2, B_), 256, SMF * sizeof(float)>>>(b_def, out);
    k_stats<<<1, 64>>>();
    k_norm<<<4096, 256>>>(out, gn_w, gn_b);
}

// round 5
// speedup vs baseline: 1.4740x; 1.4740x over previous
#include <cuda_runtime.h>
#include <math.h>

#define B_ 4
#define C_ 64
#define H_ 128
#define W_ 128
#define HW_ (H_*W_)
#define O_ 64

// Packed f32x2 helpers (Blackwell)
#define FMA2(acc, a, b) asm("fma.rn.f32x2 %0, %1, %2, %0;" : "+l"(acc) : "l"(a), "l"(b))
#define DUP2(dst, f)    asm("mov.b64 %0, {%1, %1};" : "=l"(dst) : "f"(f))
#define UNPK2(lo, hi, v) asm("mov.b64 {%0, %1}, %2;" : "=f"(lo), "=f"(hi) : "l"(v))

// Scratch
__device__ __align__(16) float g_xt[B_*HW_*C_];       // x in NHWC
__device__ __align__(16) float g_off[B_*HW_*18];      // offsets [b][h][w][18]
__device__ __align__(16) float g_wdt[9*C_*O_];        // w_def [k][c][o]
__device__ __align__(16) float g_partial[256*2*16*2]; // [blk][half][group][2]
__device__ __align__(16) float g_stats[B_*16*2];      // mu, inv_std

// ---------------- K0: NCHW -> NHWC transpose ----------------
__global__ void k_transpose(const float* __restrict__ x) {
    __shared__ float tile[32][33];
    int b  = blockIdx.z;
    int c0 = blockIdx.y * 32;
    int p0 = blockIdx.x * 32;
    int tx = threadIdx.x, ty = threadIdx.y;
    tile[ty][tx] = x[(b*C_ + c0 + ty)*HW_ + p0 + tx];
    __syncthreads();
    g_xt[(b*HW_ + p0 + ty)*C_ + c0 + tx] = tile[tx][ty];
}

// ---------------- Kw: w_def [o][c][3][3] -> [k][c][o] ----------------
__global__ void k_wreorder(const float* __restrict__ w_def) {
    int i = blockIdx.x * 256 + threadIdx.x;
    if (i < 9*64*64) {
        int o = i & 63;
        int c = (i >> 6) & 63;
        int k = i >> 12;
        g_wdt[i] = w_def[(o*64 + c)*9 + k];
    }
}

// ---------------- K1: offset conv (64 -> 18 ch, 3x3, pad 1) ----------------
__global__ void __launch_bounds__(128) k_offconv(const float* __restrict__ x,
                                                 const float* __restrict__ w_off,
                                                 const float* __restrict__ b_off) {
    __shared__ __align__(16) float ws[64*9*20];
    int h = blockIdx.x, b = blockIdx.y;
    int tid = threadIdx.x;

    for (int i = tid; i < 64*9*20; i += 128) ws[i] = 0.f;
    __syncthreads();
    for (int i = tid; i < 64*9*18; i += 128) {
        int o = i % 18;
        int cj = i / 18;
        int c = cj / 9, j = cj % 9;
        ws[cj*20 + o] = w_off[(o*64 + c)*9 + j];
    }
    __syncthreads();

    int w = tid;
    unsigned long long acc[10];
#pragma unroll
    for (int q = 0; q < 10; q++) acc[q] = 0ull;

    const float* xb = x + (size_t)b * C_ * HW_;
    bool wl = (w > 0), wr = (w < W_-1);

    for (int c = 0; c < C_; c++) {
        const float* xc = xb + c*HW_;
        float xv[9];
#pragma unroll
        for (int jy = 0; jy < 3; jy++) {
            int y = h + jy - 1;
            bool yv = (y >= 0 && y < H_);
            const float* row = xc + y*W_;
            xv[jy*3+0] = (yv && wl) ? row[w-1] : 0.f;
            xv[jy*3+1] =  yv        ? row[w]   : 0.f;
            xv[jy*3+2] = (yv && wr) ? row[w+1] : 0.f;
        }
#pragma unroll
        for (int j = 0; j < 9; j++) {
            unsigned long long v2;
            DUP2(v2, xv[j]);
            const ulonglong2* wp = (const ulonglong2*)&ws[(c*9 + j)*20];
#pragma unroll
            for (int q = 0; q < 5; q++) {
                ulonglong2 wv = wp[q];
                FMA2(acc[2*q+0], wv.x, v2);
                FMA2(acc[2*q+1], wv.y, v2);
            }
        }
    }

    float* op = &g_off[((size_t)(b*H_ + h)*W_ + w)*18];
#pragma unroll
    for (int q = 0; q < 9; q++) {
        float lo, hi;
        UNPK2(lo, hi, acc[q]);
        op[2*q+0] = lo + b_off[2*q+0];
        op[2*q+1] = hi + b_off[2*q+1];
    }
}

// ---------------- K2: pipelined deformable sample + GEMM ----------------
// Block = 2 rows (256 px), 256 threads, 2 blocks/SM (single wave of 256 blocks).
// 18 units (tap x 32-channel half). Phase p: gather(unit p) interleaved with
// GEMM(unit p-1); weights for unit p copied into smem during phase p.
// smem (floats):
//   sbuf[2]  : 32c x 256px : 2 x 8192
//   swd[2]   : 32c x 64o   : 2 x 2048
//   saddr[2] : 4 x 256 int : 2 x 1024
//   sbw[2]   : 4 x 256     : 2 x 1024
#define SBUF0  0
#define SBUF1  8192
#define SWD0   16384
#define SWD1   18432
#define SADDR0 20480
#define SADDR1 21504
#define SBW0   22528
#define SBW1   23552
#define SMF    24576   // 96 KB

__device__ __forceinline__ void comp_addr(float* sm, int k, int par,
                                          int h_a, int w_a, const float* offp, int tid) {
    int*   sa  = (int*)(sm + (par ? SADDR1 : SADDR0));
    float* swt = sm + (par ? SBW1 : SBW0);
    float dy = offp[2*k], dx = offp[2*k+1];
    float py  = (float)(h_a + k/3 - 1) + dy;
    float pxf = (float)(w_a + k%3 - 1) + dx;
    float y0f = floorf(py), x0f = floorf(pxf);
    float wy = py - y0f, wx = pxf - x0f;
    int y0 = (int)y0f, x0 = (int)x0f;
    int y1 = y0 + 1, x1 = x0 + 1;
    float vy0 = (y0 >= 0 && y0 < H_) ? 1.f : 0.f;
    float vy1 = (y1 >= 0 && y1 < H_) ? 1.f : 0.f;
    float vx0 = (x0 >= 0 && x0 < W_) ? 1.f : 0.f;
    float vx1 = (x1 >= 0 && x1 < W_) ? 1.f : 0.f;
    int y0c = min(max(y0,0),H_-1), y1c = min(max(y1,0),H_-1);
    int x0c = min(max(x0,0),W_-1), x1c = min(max(x1,0),W_-1);
    sa[0*256+tid] = (y0c*W_ + x0c)*C_;  swt[0*256+tid] = (1.f-wy)*(1.f-wx)*vy0*vx0;
    sa[1*256+tid] = (y0c*W_ + x1c)*C_;  swt[1*256+tid] = (1.f-wy)*wx*vy0*vx1;
    sa[2*256+tid] = (y1c*W_ + x0c)*C_;  swt[2*256+tid] = wy*(1.f-wx)*vy1*vx0;
    sa[3*256+tid] = (y1c*W_ + x1c)*C_;  swt[3*256+tid] = wy*wx*vy1*vx1;
}

__global__ void __launch_bounds__(256, 2) k_main(const float* __restrict__ b_def,
                                                 float* __restrict__ out) {
    extern __shared__ float sm[];
    int hb = blockIdx.x;
    int b  = blockIdx.y;
    int tid = threadIdx.x;
    int warp = tid >> 5, col = tid & 31;
    int halfw = warp >> 2;
    int o0 = (warp & 3) * 16;
    int i4 = halfw*32 + col;
    int g8 = tid >> 3, l8 = tid & 7;

    int row_a = tid >> 7;
    int w_a = tid & 127;
    int h_a = hb*2 + row_a;
    const float* offp = g_off + ((size_t)((b*H_ + h_a)*W_) + w_a)*18;
    const float* xb = g_xt + (size_t)b * HW_ * C_;

    unsigned long long acc[16][2];
#pragma unroll
    for (int i = 0; i < 16; i++) { acc[i][0] = 0ull; acc[i][1] = 0ull; }

    comp_addr(sm, 0, 0, h_a, w_a, offp, tid);
    __syncthreads();

#pragma unroll 1
    for (int p = 0; p < 19; p++) {
        bool do_g = (p < 18), do_m = (p >= 1);
        int kg = p >> 1, hg = p & 1;
        const int*   sa   = (const int*)(sm + ((kg&1) ? SADDR1 : SADDR0));
        const float* swt  = sm + ((kg&1) ? SBW1 : SBW0);
        float*       sbw  = sm + ((p&1)  ? SBUF1 : SBUF0);
        const float* sbr  = sm + (((p-1)&1) ? SBUF1 : SBUF0);
        const float* swdr = sm + (((p-1)&1) ? SWD1 : SWD0);
        int chb = hg*32 + l8*4;

        // copy weights for unit p into swd[p&1] (read next phase)
        if (do_g) {
            const float4* src = (const float4*)(g_wdt + (size_t)(kg*64 + hg*32)*64);
            float4* dst = (float4*)(sm + ((p&1) ? SWD1 : SWD0));
            dst[tid]       = src[tid];
            dst[tid + 256] = src[tid + 256];
        }

#pragma unroll
        for (int pass = 0; pass < 8; pass++) {
            int pxi = pass*32 + g8;
            float4 v0, v1, v2, v3;
            float bw0, bw1, bw2, bw3;
            if (do_g) {
                int a0 = sa[pxi], a1 = sa[256+pxi], a2 = sa[512+pxi], a3 = sa[768+pxi];
                bw0 = swt[pxi]; bw1 = swt[256+pxi]; bw2 = swt[512+pxi]; bw3 = swt[768+pxi];
                v0 = *(const float4*)(xb + a0 + chb);
                v1 = *(const float4*)(xb + a1 + chb);
                v2 = *(const float4*)(xb + a2 + chb);
                v3 = *(const float4*)(xb + a3 + chb);
            }
            if (do_m) {
#pragma unroll
                for (int j = 0; j < 4; j++) {
                    int cc = pass*4 + j;                 // local channel 0..31
                    ulonglong2 s2 = *(const ulonglong2*)&sbr[cc*256 + ((i4 ^ (cc>>2)) << 2)];
                    float4 wa = *(const float4*)&swdr[cc*64 + o0];
                    float4 wb = *(const float4*)&swdr[cc*64 + o0 + 4];
                    float4 wc = *(const float4*)&swdr[cc*64 + o0 + 8];
                    float4 wd = *(const float4*)&swdr[cc*64 + o0 + 12];
                    unsigned long long d0,d1,d2,d3;
                    DUP2(d0, wa.x); DUP2(d1, wa.y); DUP2(d2, wa.z); DUP2(d3, wa.w);
                    FMA2(acc[0][0], d0, s2.x); FMA2(acc[0][1], d0, s2.y);
                    FMA2(acc[1][0], d1, s2.x); FMA2(acc[1][1], d1, s2.y);
                    FMA2(acc[2][0], d2, s2.x); FMA2(acc[2][1], d2, s2.y);
                    FMA2(acc[3][0], d3, s2.x); FMA2(acc[3][1], d3, s2.y);
                    DUP2(d0, wb.x); DUP2(d1, wb.y); DUP2(d2, wb.z); DUP2(d3, wb.w);
                    FMA2(acc[4][0], d0, s2.x); FMA2(acc[4][1], d0, s2.y);
                    FMA2(acc[5][0], d1, s2.x); FMA2(acc[5][1], d1, s2.y);
                    FMA2(acc[6][0], d2, s2.x); FMA2(acc[6][1], d2, s2.y);
                    FMA2(acc[7][0], d3, s2.x); FMA2(acc[7][1], d3, s2.y);
                    DUP2(d0, wc.x); DUP2(d1, wc.y); DUP2(d2, wc.z); DUP2(d3, wc.w);
                    FMA2(acc[8][0],  d0, s2.x); FMA2(acc[8][1],  d0, s2.y);
                    FMA2(acc[9][0],  d1, s2.x); FMA2(acc[9][1],  d1, s2.y);
                    FMA2(acc[10][0], d2, s2.x); FMA2(acc[10][1], d2, s2.y);
                    FMA2(acc[11][0], d3, s2.x); FMA2(acc[11][1], d3, s2.y);
                    DUP2(d0, wd.x); DUP2(d1, wd.y); DUP2(d2, wd.z); DUP2(d3, wd.w);
                    FMA2(acc[12][0], d0, s2.x); FMA2(acc[12][1], d0, s2.y);
                    FMA2(acc[13][0], d1, s2.x); FMA2(acc[13][1], d1, s2.y);
                    FMA2(acc[14][0], d2, s2.x); FMA2(acc[14][1], d2, s2.y);
                    FMA2(acc[15][0], d3, s2.x); FMA2(acc[15][1], d3, s2.y);
                }
            }
            if (do_g) {
                float sx = bw0*v0.x + bw1*v1.x + bw2*v2.x + bw3*v3.x;
                float sy = bw0*v0.y + bw1*v1.y + bw2*v2.y + bw3*v3.y;
                float sz = bw0*v0.z + bw1*v1.z + bw2*v2.z + bw3*v3.z;
                float sw = bw0*v0.w + bw1*v1.w + bw2*v2.w + bw3*v3.w;
                int scg = (((pxi>>2) ^ l8) << 2) + (pxi & 3);
                float* d = &sbw[(l8*4)*256 + scg];
                d[0]   = sx;
                d[256] = sy;
                d[512] = sz;
                d[768] = sw;
            }
        }
        if ((p & 1) && p < 17) {
            int tn = (p+1) >> 1;
            comp_addr(sm, tn, tn & 1, h_a, w_a, offp, tid);
        }
        __syncthreads();
    }

    // ---- epilogue: bias, store pre-GN, per-group partials ----
    float sg[4] = {0,0,0,0}, qg[4] = {0,0,0,0};
    int h_out = hb*2 + halfw;
    float* outb = out + (size_t)b * O_ * HW_ + h_out*W_ + col*4;
#pragma unroll
    for (int i = 0; i < 16; i++) {
        int o = o0 + i;
        float bo = b_def[o];
        float4 v;
        UNPK2(v.x, v.y, acc[i][0]);
        UNPK2(v.z, v.w, acc[i][1]);
        v.x += bo; v.y += bo; v.z += bo; v.w += bo;
        *(float4*)(outb + (size_t)o * HW_) = v;
        int gi = i >> 2;
        sg[gi] += v.x + v.y + v.z + v.w;
        qg[gi] += v.x*v.x + v.y*v.y + v.z*v.z + v.w*v.w;
    }
#pragma unroll
    for (int off = 16; off > 0; off >>= 1) {
#pragma unroll
        for (int gi = 0; gi < 4; gi++) {
            sg[gi] += __shfl_xor_sync(0xffffffffu, sg[gi], off);
            qg[gi] += __shfl_xor_sync(0xffffffffu, qg[gi], off);
        }
    }
    if (col == 0) {
        int blk = b*64 + hb;
        float* pp = &g_partial[(size_t)((blk*2 + halfw)*16)*2];
#pragma unroll
        for (int gi = 0; gi < 4; gi++) {
            int grp = (o0 >> 2) + gi;
            pp[grp*2 + 0] = sg[gi];
            pp[grp*2 + 1] = qg[gi];
        }
    }
}

// ---------------- K3: finalize GN stats ----------------
__global__ void k_stats() {
    int t = threadIdx.x;
    if (t >= 64) return;
    int b = t >> 4, gg = t & 15;
    float s = 0.f, q = 0.f;
    for (int e = 0; e < 128; e++) {
        int blk = b*64 + (e >> 1);
        const float* pp = &g_partial[(size_t)((blk*2 + (e&1))*16 + gg)*2];
        s += pp[0];
        q += pp[1];
    }
    const float N = 4.f * (float)HW_;
    float mu = s / N;
    float var = q / N - mu*mu;
    g_stats[t*2 + 0] = mu;
    g_stats[t*2 + 1] = rsqrtf(var + 1e-5f);
}

// ---------------- K4: GN affine + LeakyReLU ----------------
__global__ void k_norm(float* __restrict__ out,
                       const float* __restrict__ gn_w,
                       const float* __restrict__ gn_b) {
    int i = blockIdx.x * 256 + threadIdx.x;
    int base = i * 4;
    int c = (base >> 14) & 63;
    int b = base >> 20;
    int g = c >> 2;
    float mu  = g_stats[(b*16 + g)*2 + 0];
    float inv = g_stats[(b*16 + g)*2 + 1];
    float sc = gn_w[c] * inv;
    float sh = gn_b[c] - mu * sc;
    float4 v = ((float4*)out)[i];
    v.x = v.x*sc + sh; v.x = (v.x >= 0.f) ? v.x : 0.2f*v.x;
    v.y = v.y*sc + sh; v.y = (v.y >= 0.f) ? v.y : 0.2f*v.y;
    v.z = v.z*sc + sh; v.z = (v.z >= 0.f) ? v.z : 0.2f*v.z;
    v.w = v.w*sc + sh; v.w = (v.w >= 0.f) ? v.w : 0.2f*v.w;
    ((float4*)out)[i] = v;
}

extern "C" void kernel_launch(void* const* d_in, const int* in_sizes, int n_in,
                              void* d_out, int out_size) {
    const float* x     = (const float*)d_in[0];
    const float* w_off = (const float*)d_in[1];
    const float* b_off = (const float*)d_in[2];
    const float* w_def = (const float*)d_in[3];
    const float* b_def = (const float*)d_in[4];
    const float* gn_w  = (const float*)d_in[5];
    const float* gn_b  = (const float*)d_in[6];
    float* out = (float*)d_out;

    cudaFuncSetAttribute(k_main, cudaFuncAttributeMaxDynamicSharedMemorySize,
                         SMF * (int)sizeof(float));

    k_transpose<<<dim3(HW_/32, C_/32, B_), dim3(32, 32)>>>(x);
    k_wreorder<<<144, 256>>>(w_def);
    k_offconv<<<dim3(H_, B_), 128>>>(x, w_off, b_off);
    k_main<<<dim3(H_/2, B_), 256, SMF * sizeof(float)>>>(b_def, out);
    k_stats<<<1, 64>>>();
    k_norm<<<4096, 256>>>(out, gn_w, gn_b);
}

// round 7
// speedup vs baseline: 1.6419x; 1.1139x over previous
#include <cuda_runtime.h>
#include <math.h>
#include <stdint.h>

#define B_ 4
#define C_ 64
#define H_ 128
#define W_ 128
#define HW_ (H_*W_)
#define O_ 64

// Packed f32x2 helpers (Blackwell)
#define FMA2(acc, a, b) asm("fma.rn.f32x2 %0, %1, %2, %0;" : "+l"(acc) : "l"(a), "l"(b))
#define DUP2(dst, f)    asm("mov.b64 %0, {%1, %1};" : "=l"(dst) : "f"(f))
#define UNPK2(lo, hi, v) asm("mov.b64 {%0, %1}, %2;" : "=f"(lo), "=f"(hi) : "l"(v))

// Scratch
__device__ __align__(16) float g_xt[B_*HW_*C_];       // x in NHWC
__device__ __align__(16) float g_off[B_*HW_*18];      // offsets [b][h][w][18]
__device__ __align__(16) float g_wdt[9*C_*O_];        // w_def [k][c][o]
__device__ __align__(16) float g_partial[B_*H_*16*2]; // [b][h][group][2]
__device__ __align__(16) float g_stats[B_*16*2];      // mu, inv_std

// ---------------- K0: NCHW -> NHWC transpose ----------------
__global__ void k_transpose(const float* __restrict__ x) {
    __shared__ float tile[32][33];
    int b  = blockIdx.z;
    int c0 = blockIdx.y * 32;
    int p0 = blockIdx.x * 32;
    int tx = threadIdx.x, ty = threadIdx.y;
    tile[ty][tx] = x[(b*C_ + c0 + ty)*HW_ + p0 + tx];
    __syncthreads();
    g_xt[(b*HW_ + p0 + ty)*C_ + c0 + tx] = tile[tx][ty];
}

// ---------------- Kw: w_def [o][c][3][3] -> [k][c][o] ----------------
__global__ void k_wreorder(const float* __restrict__ w_def) {
    int i = blockIdx.x * 256 + threadIdx.x;
    if (i < 9*64*64) {
        int o = i & 63;
        int c = (i >> 6) & 63;
        int k = i >> 12;
        g_wdt[i] = w_def[(o*64 + c)*9 + k];
    }
}

// ---------------- K1: offset conv (64 -> 18 ch, 3x3, pad 1) ----------------
// Block = 2 image rows, 256 threads (one per pixel).
__global__ void __launch_bounds__(256) k_offconv(const float* __restrict__ x,
                                                 const float* __restrict__ w_off,
                                                 const float* __restrict__ b_off) {
    __shared__ __align__(16) float ws[64*9*20];
    int hb = blockIdx.x, b = blockIdx.y;
    int tid = threadIdx.x;

    for (int i = tid; i < 64*9*20; i += 256) ws[i] = 0.f;
    __syncthreads();
    for (int i = tid; i < 64*9*18; i += 256) {
        int o = i % 18;
        int cj = i / 18;
        int c = cj / 9, j = cj % 9;
        ws[cj*20 + o] = w_off[(o*64 + c)*9 + j];
    }
    __syncthreads();

    int h = hb*2 + (tid >> 7);
    int w = tid & 127;
    unsigned long long acc[10];
#pragma unroll
    for (int q = 0; q < 10; q++) acc[q] = 0ull;

    const float* xb = x + (size_t)b * C_ * HW_;
    bool wl = (w > 0), wr = (w < W_-1);

    for (int c = 0; c < C_; c++) {
        const float* xc = xb + c*HW_;
        float xv[9];
#pragma unroll
        for (int jy = 0; jy < 3; jy++) {
            int y = h + jy - 1;
            bool yv = (y >= 0 && y < H_);
            const float* row = xc + y*W_;
            xv[jy*3+0] = (yv && wl) ? row[w-1] : 0.f;
            xv[jy*3+1] =  yv        ? row[w]   : 0.f;
            xv[jy*3+2] = (yv && wr) ? row[w+1] : 0.f;
        }
#pragma unroll
        for (int j = 0; j < 9; j++) {
            unsigned long long v2;
            DUP2(v2, xv[j]);
            const ulonglong2* wp = (const ulonglong2*)&ws[(c*9 + j)*20];
#pragma unroll
            for (int q = 0; q < 5; q++) {
                ulonglong2 wv = wp[q];
                FMA2(acc[2*q+0], wv.x, v2);
                FMA2(acc[2*q+1], wv.y, v2);
            }
        }
    }

    float* op = &g_off[((size_t)(b*H_ + h)*W_ + w)*18];
#pragma unroll
    for (int q = 0; q < 9; q++) {
        float lo, hi;
        UNPK2(lo, hi, acc[q]);
        op[2*q+0] = lo + b_off[2*q+0];
        op[2*q+1] = hi + b_off[2*q+1];
    }
}

// ---------------- K2: pipelined deformable sample + GEMM ----------------
// Block = 1 row (128 px), 128 threads, 4 blocks/SM.
// 18 units (tap x 32-channel half). Phase p: gather(unit p) interleaved with
// GEMM(unit p-1). Sample tiles + weight tiles double-buffered; addr single.
// smem (floats):
#define SBUF0  0        // 32c x 128px
#define SBUF1  4096
#define SWD0   8192     // 32c x 64o
#define SWD1   10240
#define SADDR  12288    // 4 x 128 int
#define SBW    12800    // 4 x 128 float
#define SMF    13312    // 53248 bytes

__global__ void __launch_bounds__(128, 4) k_main(const float* __restrict__ b_def,
                                                 float* __restrict__ out) {
    extern __shared__ float sm[];
    int h = blockIdx.x;
    int b = blockIdx.y;
    int tid = threadIdx.x;
    int warp = tid >> 5, col = tid & 31;
    int o0 = warp * 16;
    int g8 = tid >> 3, l8 = tid & 7;   // gather: pixel-in-pass, channel-group

    const float* offp = g_off + ((size_t)((b*H_ + h)*W_) + tid)*18;
    const float* xb = g_xt + (size_t)b * HW_ * C_;
    int*   s_addr = (int*)(sm + SADDR);
    float* s_bw   = sm + SBW;

    unsigned long long acc[8][4];   // [o-pair][px]
#pragma unroll
    for (int i = 0; i < 8; i++)
#pragma unroll
        for (int j = 0; j < 4; j++) acc[i][j] = 0ull;

#pragma unroll 1
    for (int p = 0; p < 19; p++) {
        bool do_g = (p < 18), do_m = (p >= 1);
        int kg = p >> 1, hg = p & 1;

        // even phases: compute this tap's corner addresses + bilinear weights
        if (hg == 0 && do_g) {
            int w_a = tid;
            float dy = offp[2*kg], dx = offp[2*kg+1];
            float py  = (float)(h + kg/3 - 1) + dy;
            float pxf = (float)(w_a + kg%3 - 1) + dx;
            float y0f = floorf(py), x0f = floorf(pxf);
            float wy = py - y0f, wx = pxf - x0f;
            int y0 = (int)y0f, x0 = (int)x0f;
            int y1 = y0 + 1, x1 = x0 + 1;
            float vy0 = (y0 >= 0 && y0 < H_) ? 1.f : 0.f;
            float vy1 = (y1 >= 0 && y1 < H_) ? 1.f : 0.f;
            float vx0 = (x0 >= 0 && x0 < W_) ? 1.f : 0.f;
            float vx1 = (x1 >= 0 && x1 < W_) ? 1.f : 0.f;
            int y0c = min(max(y0,0),H_-1), y1c = min(max(y1,0),H_-1);
            int x0c = min(max(x0,0),W_-1), x1c = min(max(x1,0),W_-1);
            s_addr[0*128+tid] = (y0c*W_ + x0c)*C_;  s_bw[0*128+tid] = (1.f-wy)*(1.f-wx)*vy0*vx0;
            s_addr[1*128+tid] = (y0c*W_ + x1c)*C_;  s_bw[1*128+tid] = (1.f-wy)*wx*vy0*vx1;
            s_addr[2*128+tid] = (y1c*W_ + x0c)*C_;  s_bw[2*128+tid] = wy*(1.f-wx)*vy1*vx0;
            s_addr[3*128+tid] = (y1c*W_ + x1c)*C_;  s_bw[3*128+tid] = wy*wx*vy1*vx1;
            __syncthreads();
        }

        float*       sbw  = sm + ((p&1)     ? SBUF1 : SBUF0);
        const float* sbr  = sm + (((p-1)&1) ? SBUF1 : SBUF0);
        const float* swdr = sm + (((p-1)&1) ? SWD1  : SWD0);
        int chb = hg*32 + l8*4;

        // copy weights for unit p into swd[p&1] (read next phase)
        if (do_g) {
            const float4* src = (const float4*)(g_wdt + (size_t)(kg*64 + hg*32)*64);
            float4* dst = (float4*)(sm + ((p&1) ? SWD1 : SWD0));
#pragma unroll
            for (int i = 0; i < 4; i++) dst[tid + i*128] = src[tid + i*128];
        }

#pragma unroll
        for (int pass = 0; pass < 8; pass++) {
            int pxi = pass*16 + g8;
            float4 v0, v1, v2, v3;
            float bw0, bw1, bw2, bw3;
            if (do_g) {
                int a0 = s_addr[pxi], a1 = s_addr[128+pxi], a2 = s_addr[256+pxi], a3 = s_addr[384+pxi];
                bw0 = s_bw[pxi]; bw1 = s_bw[128+pxi]; bw2 = s_bw[256+pxi]; bw3 = s_bw[384+pxi];
                v0 = *(const float4*)(xb + a0 + chb);
                v1 = *(const float4*)(xb + a1 + chb);
                v2 = *(const float4*)(xb + a2 + chb);
                v3 = *(const float4*)(xb + a3 + chb);
            }
            if (do_m) {
#pragma unroll
                for (int j = 0; j < 4; j++) {
                    int cc = pass*4 + j;                 // local channel 0..31
                    float4 s4 = *(const float4*)&sbr[cc*128 + ((col ^ (cc>>2)) << 2)];
                    unsigned long long d0, d1, d2, d3;
                    DUP2(d0, s4.x); DUP2(d1, s4.y); DUP2(d2, s4.z); DUP2(d3, s4.w);
                    const ulonglong2* wp = (const ulonglong2*)&swdr[cc*64 + o0];
                    ulonglong2 wA = wp[0], wB = wp[1], wC = wp[2], wD = wp[3];
                    FMA2(acc[0][0], wA.x, d0); FMA2(acc[0][1], wA.x, d1);
                    FMA2(acc[0][2], wA.x, d2); FMA2(acc[0][3], wA.x, d3);
                    FMA2(acc[1][0], wA.y, d0); FMA2(acc[1][1], wA.y, d1);
                    FMA2(acc[1][2], wA.y, d2); FMA2(acc[1][3], wA.y, d3);
                    FMA2(acc[2][0], wB.x, d0); FMA2(acc[2][1], wB.x, d1);
                    FMA2(acc[2][2], wB.x, d2); FMA2(acc[2][3], wB.x, d3);
                    FMA2(acc[3][0], wB.y, d0); FMA2(acc[3][1], wB.y, d1);
                    FMA2(acc[3][2], wB.y, d2); FMA2(acc[3][3], wB.y, d3);
                    FMA2(acc[4][0], wC.x, d0); FMA2(acc[4][1], wC.x, d1);
                    FMA2(acc[4][2], wC.x, d2); FMA2(acc[4][3], wC.x, d3);
                    FMA2(acc[5][0], wC.y, d0); FMA2(acc[5][1], wC.y, d1);
                    FMA2(acc[5][2], wC.y, d2); FMA2(acc[5][3], wC.y, d3);
                    FMA2(acc[6][0], wD.x, d0); FMA2(acc[6][1], wD.x, d1);
                    FMA2(acc[6][2], wD.x, d2); FMA2(acc[6][3], wD.x, d3);
                    FMA2(acc[7][0], wD.y, d0); FMA2(acc[7][1], wD.y, d1);
                    FMA2(acc[7][2], wD.y, d2); FMA2(acc[7][3], wD.y, d3);
                }
            }
            if (do_g) {
                float sx = bw0*v0.x + bw1*v1.x + bw2*v2.x + bw3*v3.x;
                float sy = bw0*v0.y + bw1*v1.y + bw2*v2.y + bw3*v3.y;
                float sz = bw0*v0.z + bw1*v1.z + bw2*v2.z + bw3*v3.z;
                float sw = bw0*v0.w + bw1*v1.w + bw2*v2.w + bw3*v3.w;
                int scg = (((pxi>>2) ^ l8) << 2) + (pxi & 3);
                float* d = &sbw[(l8*4)*128 + scg];
                d[0]   = sx;
                d[128] = sy;
                d[256] = sz;
                d[384] = sw;
            }
        }
        __syncthreads();
    }

    // ---- epilogue: bias, store pre-GN, per-group partials ----
    float sg[4] = {0,0,0,0}, qg[4] = {0,0,0,0};
    float* outb = out + (size_t)b * O_ * HW_ + h*W_ + col*4;
#pragma unroll
    for (int j = 0; j < 8; j++) {
        int oe = o0 + 2*j, oo = oe + 1;
        float be = b_def[oe], bo = b_def[oo];
        float4 ve, vo;
        UNPK2(ve.x, vo.x, acc[j][0]);
        UNPK2(ve.y, vo.y, acc[j][1]);
        UNPK2(ve.z, vo.z, acc[j][2]);
        UNPK2(ve.w, vo.w, acc[j][3]);
        ve.x += be; ve.y += be; ve.z += be; ve.w += be;
        vo.x += bo; vo.y += bo; vo.z += bo; vo.w += bo;
        *(float4*)(outb + (size_t)oe * HW_) = ve;
        *(float4*)(outb + (size_t)oo * HW_) = vo;
        int gi = j >> 1;
        sg[gi] += ve.x + ve.y + ve.z + ve.w + vo.x + vo.y + vo.z + vo.w;
        qg[gi] += ve.x*ve.x + ve.y*ve.y + ve.z*ve.z + ve.w*ve.w
                + vo.x*vo.x + vo.y*vo.y + vo.z*vo.z + vo.w*vo.w;
    }
#pragma unroll
    for (int off = 16; off > 0; off >>= 1) {
#pragma unroll
        for (int gi = 0; gi < 4; gi++) {
            sg[gi] += __shfl_xor_sync(0xffffffffu, sg[gi], off);
            qg[gi] += __shfl_xor_sync(0xffffffffu, qg[gi], off);
        }
    }
    if (col == 0) {
        float* pp = &g_partial[(size_t)((b*H_ + h)*16)*2];
#pragma unroll
        for (int gi = 0; gi < 4; gi++) {
            int grp = warp*4 + gi;
            pp[grp*2 + 0] = sg[gi];
            pp[grp*2 + 1] = qg[gi];
        }
    }
}

// ---------------- K3: finalize GN stats ----------------
__global__ void k_stats() {
    int t = threadIdx.x;
    if (t >= 64) return;
    int b = t >> 4, gg = t & 15;
    float s = 0.f, q = 0.f;
    for (int h = 0; h < H_; h++) {
        const float* pp = &g_partial[(size_t)(((b*H_ + h)*16) + gg)*2];
        s += pp[0];
        q += pp[1];
    }
    const float N = 4.f * (float)HW_;
    float mu = s / N;
    float var = q / N - mu*mu;
    g_stats[t*2 + 0] = mu;
    g_stats[t*2 + 1] = rsqrtf(var + 1e-5f);
}

// ---------------- K4: GN affine + LeakyReLU ----------------
__global__ void k_norm(float* __restrict__ out,
                       const float* __restrict__ gn_w,
                       const float* __restrict__ gn_b) {
    int i = blockIdx.x * 256 + threadIdx.x;
    int base = i * 4;
    int c = (base >> 14) & 63;
    int b = base >> 20;
    int g = c >> 2;
    float mu  = g_stats[(b*16 + g)*2 + 0];
    float inv = g_stats[(b*16 + g)*2 + 1];
    float sc = gn_w[c] * inv;
    float sh = gn_b[c] - mu * sc;
    float4 v = ((float4*)out)[i];
    v.x = v.x*sc + sh; v.x = (v.x >= 0.f) ? v.x : 0.2f*v.x;
    v.y = v.y*sc + sh; v.y = (v.y >= 0.f) ? v.y : 0.2f*v.y;
    v.z = v.z*sc + sh; v.z = (v.z >= 0.f) ? v.z : 0.2f*v.z;
    v.w = v.w*sc + sh; v.w = (v.w >= 0.f) ? v.w : 0.2f*v.w;
    ((float4*)out)[i] = v;
}

extern "C" void kernel_launch(void* const* d_in, const int* in_sizes, int n_in,
                              void* d_out, int out_size) {
    const float* x     = (const float*)d_in[0];
    const float* w_off = (const float*)d_in[1];
    const float* b_off = (const float*)d_in[2];
    const float* w_def = (const float*)d_in[3];
    const float* b_def = (const float*)d_in[4];
    const float* gn_w  = (const float*)d_in[5];
    const float* gn_b  = (const float*)d_in[6];
    float* out = (float*)d_out;

    cudaFuncSetAttribute(k_main, cudaFuncAttributeMaxDynamicSharedMemorySize,
                         SMF * (int)sizeof(float));

    k_transpose<<<dim3(HW_/32, C_/32, B_), dim3(32, 32)>>>(x);
    k_wreorder<<<144, 256>>>(w_def);
    k_offconv<<<dim3(H_/2, B_), 256>>>(x, w_off, b_off);
    k_main<<<dim3(H_, B_), 128, SMF * sizeof(float)>>>(b_def, out);
    k_stats<<<1, 64>>>();
    k_norm<<<4096, 256>>>(out, gn_w, gn_b);
}